// round 16
// baseline (speedup 1.0000x reference)
#include <cuda_runtime.h>
#include <cuda_bf16.h>
#include <stdint.h>

#define NTOK   16384
#define DIM    2048
#define NE     64
#define KTOP   8
#define ALPHA_C 0.001f

#define TM     64                  // tokens per CTA
#define NT     384                 // warps 0-7: HMMA domain; warps 8-11: FFMA2 domain
#define KC     64                  // HMMA k-chunk
#define NCH_H  18                  // HMMA chunks: k in [0, 1152)
#define KSB    (NCH_H * KC)        // 1152: SIMT k base
#define KC2    32                  // SIMT k-chunk
#define NCS    ((DIM - KSB) / KC2) // 28 SIMT chunks
#define NBLK   (NTOK / TM)         // 256 CTAs, 1/SM resident
#define TAU    1e-4f               // near-tie fallback threshold (logit gap)

// ---- HMMA smem (bf16, pitch 72 bf16 = 144B; ldmatrix rows -> banks 0,4,..,28) ----
#define APB    144
#define ABASE(b, t) ((b) * 18432 + (t) * 9216)            // A: 2 buf x 2 term
#define BBASE(b, t) (36864 + (b) * 18432 + (t) * 9216)    // B: ring-3 x 2 term
// ---- SIMT smem (fp32) ----
#define SH_OFF 92160               // hs2[2][32][68] = 17408 B
#define SW_OFF 109568              // ws[2][64][36]  = 18432 B
#define DYN_BYTES 128000           // > 114 KB -> guaranteed 1 CTA/SM
// epilogue scratch (float offsets within dead A region; logits uses [0,4160))
#define PR_OFF 4608
#define RC_OFF 4864
#define RP_OFF 5120

__device__ float g_cnt_part[NBLK][NE];
__device__ float g_prob_part[NBLK][NE];
__device__ unsigned int g_sync = 0;   // atomicInc wraps each launch -> graph-replay safe
__device__ __align__(16) __nv_bfloat16 g_Whi[NE * DIM];   // 256 KB
__device__ __align__(16) __nv_bfloat16 g_Wlo[NE * DIM];   // 256 KB

static __device__ __forceinline__ uint32_t smem_u32(const void* p) {
    uint32_t a;
    asm("{ .reg .u64 t; cvta.to.shared.u64 t, %1; cvt.u32.u64 %0, t; }" : "=r"(a) : "l"(p));
    return a;
}
#define BARN(id, n) asm volatile("bar.sync %0, %1;" :: "r"(id), "r"(n) : "memory")

#define LDSM4(r, a) \
    asm volatile("ldmatrix.sync.aligned.m8n8.x4.shared.b16 {%0,%1,%2,%3}, [%4];" \
        : "=r"((r)[0]), "=r"((r)[1]), "=r"((r)[2]), "=r"((r)[3]) : "r"(a))
#define MMA(d, a, b) \
    asm volatile("mma.sync.aligned.m16n8k16.row.col.f32.bf16.bf16.f32 " \
        "{%0,%1,%2,%3}, {%4,%5,%6,%7}, {%8,%9}, {%0,%1,%2,%3};" \
        : "+f"((d)[0]), "+f"((d)[1]), "+f"((d)[2]), "+f"((d)[3]) \
        : "r"((a)[0]), "r"((a)[1]), "r"((a)[2]), "r"((a)[3]), "r"((b)[0]), "r"((b)[1]))
template <int N> static __device__ __forceinline__ void cp_wait() {
    asm volatile("cp.async.wait_group %0;" :: "n"(N) : "memory");
}

typedef unsigned long long u64;
static __device__ __forceinline__ void ffma2(u64& d, u64 a, u64 b) {
    asm("fma.rn.f32x2 %0, %1, %2, %3;" : "=l"(d) : "l"(a), "l"(b), "l"(d));
}
static __device__ __forceinline__ u64 pack2(float x) {
    u64 r; asm("mov.b64 %0, {%1, %1};" : "=l"(r) : "f"(x)); return r;
}
static __device__ __forceinline__ void unpack2(u64 v, float& lo, float& hi) {
    unsigned int a, b;
    asm("mov.b64 {%0, %1}, %2;" : "=r"(a), "=r"(b) : "l"(v));
    lo = __uint_as_float(a); hi = __uint_as_float(b);
}

static __device__ __forceinline__ void split4(float4 v, uint2& hi, uint2& lo) {
    __nv_bfloat162 h0 = __float22bfloat162_rn(make_float2(v.x, v.y));
    __nv_bfloat162 h1 = __float22bfloat162_rn(make_float2(v.z, v.w));
    float2 f0 = __bfloat1622float2(h0);
    float2 f1 = __bfloat1622float2(h1);
    __nv_bfloat162 l0 = __float22bfloat162_rn(make_float2(v.x - f0.x, v.y - f0.y));
    __nv_bfloat162 l1 = __float22bfloat162_rn(make_float2(v.z - f1.x, v.w - f1.y));
    hi.x = *reinterpret_cast<uint32_t*>(&h0);
    hi.y = *reinterpret_cast<uint32_t*>(&h1);
    lo.x = *reinterpret_cast<uint32_t*>(&l0);
    lo.y = *reinterpret_cast<uint32_t*>(&l1);
}

__global__ void wconv_kernel(const float* __restrict__ W)
{
    int i = blockIdx.x * blockDim.x + threadIdx.x;
    float4 v = ((const float4*)W)[i];
    uint2 hi, lo; split4(v, hi, lo);
    ((uint2*)g_Whi)[i] = hi;
    ((uint2*)g_Wlo)[i] = lo;
}

// ---- HMMA chunk stages (256 threads; verbatim R14) ----
static __device__ __forceinline__ void ldg_h(const float* Hb, int c, int tid, float4 (&ha)[4]) {
    const float* hp = Hb + c * KC;
#pragma unroll
    for (int g = 0; g < 4; g++) {
        int flat = tid + 256 * g, row = flat >> 4, f4 = flat & 15;
        ha[g] = *(const float4*)(hp + (size_t)row * DIM + f4 * 4);
    }
}
static __device__ __forceinline__ void sts_h(char* base, int buf, int tid, const float4 (&ha)[4]) {
#pragma unroll
    for (int g = 0; g < 4; g++) {
        int flat = tid + 256 * g, row = flat >> 4, f4 = flat & 15;
        int off = row * APB + f4 * 8;
        uint2 hi, lo;
        split4(ha[g], hi, lo);
        *(uint2*)(base + ABASE(buf, 0) + off) = hi;
        *(uint2*)(base + ABASE(buf, 1) + off) = lo;
    }
}
static __device__ __forceinline__ void b_cpasync(uint32_t dynb32, int c, int bufB, int tid) {
#pragma unroll
    for (int g = 0; g < 4; g++) {
        int flat = tid + 256 * g;
        int arr = flat >> 9, rem = flat & 511, row = rem >> 3, seg = rem & 7;
        const char* src = (const char*)(arr ? g_Wlo : g_Whi) +
                          ((size_t)row * DIM + c * KC) * 2 + seg * 16;
        uint32_t dst = dynb32 + BBASE(bufB, arr) + (uint32_t)(row * APB + seg * 16);
        asm volatile("cp.async.cg.shared.global [%0], [%1], 16;" :: "r"(dst), "l"(src) : "memory");
    }
    asm volatile("cp.async.commit_group;" ::: "memory");
}
static __device__ __forceinline__ void compute_h(uint32_t dynb32, int bA, int bB,
                                                 int wid, int lane, float (&acc)[2][4][4]) {
    const uint32_t aHi = dynb32 + ABASE(bA, 0), aLo = dynb32 + ABASE(bA, 1);
    const uint32_t bHi = dynb32 + BBASE(bB, 0), bLo = dynb32 + BBASE(bB, 1);
    const int mrow = (wid & 1) * 32;
    const int ncol = ((wid >> 1) & 1) * 32;
    const int kh   = wid >> 2;
    const uint32_t aR0 = (uint32_t)((mrow + (lane & 15)) * APB + (lane >> 4) * 16);
    const uint32_t aR1 = aR0 + (uint32_t)(16 * APB);
    const uint32_t bR0 = (uint32_t)((ncol + (lane & 7) + ((lane >> 4) & 1) * 8) * APB +
                                    ((lane >> 3) & 1) * 16);
#pragma unroll
    for (int ss = 0; ss < 2; ss++) {
        const uint32_t so = (uint32_t)((kh * 2 + ss) * 32);
        uint32_t ah0[4], ah1[4], al0[4], al1[4], bh[2][4], bl[2][4];
        LDSM4(ah0, aHi + aR0 + so);
        LDSM4(ah1, aHi + aR1 + so);
        LDSM4(al0, aLo + aR0 + so);
        LDSM4(al1, aLo + aR1 + so);
        LDSM4(bh[0], bHi + bR0 + so);
        LDSM4(bh[1], bHi + bR0 + (uint32_t)(16 * APB) + so);
        LDSM4(bl[0], bLo + bR0 + so);
        LDSM4(bl[1], bLo + bR0 + (uint32_t)(16 * APB) + so);
#pragma unroll
        for (int jp = 0; jp < 2; jp++) {
            MMA(acc[0][2 * jp],     ah0, bh[jp]);
            MMA(acc[0][2 * jp + 1], ah0, bh[jp] + 2);
            MMA(acc[1][2 * jp],     ah1, bh[jp]);
            MMA(acc[1][2 * jp + 1], ah1, bh[jp] + 2);
        }
#pragma unroll
        for (int jp = 0; jp < 2; jp++) {
            MMA(acc[0][2 * jp],     ah0, bl[jp]);
            MMA(acc[0][2 * jp + 1], ah0, bl[jp] + 2);
            MMA(acc[1][2 * jp],     ah1, bl[jp]);
            MMA(acc[1][2 * jp + 1], ah1, bl[jp] + 2);
        }
#pragma unroll
        for (int jp = 0; jp < 2; jp++) {
            MMA(acc[0][2 * jp],     al0, bh[jp]);
            MMA(acc[0][2 * jp + 1], al0, bh[jp] + 2);
            MMA(acc[1][2 * jp],     al1, bh[jp]);
            MMA(acc[1][2 * jp + 1], al1, bh[jp] + 2);
        }
    }
}

// ---- SIMT (FFMA2) stages: 128 threads, TM=64, KC2=32 (R6 mapping) ----
static __device__ __forceinline__ void simt_ldg(const float* Hb, const float* W, int k0, int stid,
                                                float4 (&hv)[4], float4 (&wv)[4]) {
    const int lrow = stid >> 1, lc = (stid & 1) * 16;
#pragma unroll
    for (int x = 0; x < 4; x++) {
        hv[x] = *(const float4*)(Hb + (size_t)lrow * DIM + k0 + lc + 4 * x);
        wv[x] = *(const float4*)(W  + (size_t)lrow * DIM + k0 + lc + 4 * x);
    }
}
static __device__ __forceinline__ void simt_sts(float* sh, float* sw, int buf, int stid,
                                                const float4 (&hv)[4], const float4 (&wv)[4]) {
    const int lrow = stid >> 1, lc = (stid & 1) * 16;
    const int tp = lrow >> 1, lane = lrow & 1;
#pragma unroll
    for (int x = 0; x < 4; x++) {
        const int c = lc + 4 * x;
        float* hrow = sh + (size_t)(buf * 32 + tp) * 68;
        hrow[2 * (c + 0) + lane] = hv[x].x;
        hrow[2 * (c + 1) + lane] = hv[x].y;
        hrow[2 * (c + 2) + lane] = hv[x].z;
        hrow[2 * (c + 3) + lane] = hv[x].w;
        *(float4*)(sw + (size_t)(buf * 64 + lrow) * 36 + c) = wv[x];
    }
}
static __device__ __forceinline__ void simt_compute(const float* sh, const float* sw, int b,
                                                    int stid, u64 (&acc2)[4][4]) {
    const int er = stid & 15, tr = stid >> 4;
#pragma unroll
    for (int k4 = 0; k4 < KC2; k4 += 4) {
        ulonglong2 h01[4], h23[4];
#pragma unroll
        for (int i = 0; i < 4; i++) {
            const float* p = sh + (size_t)(b * 32 + tr * 4 + i) * 68 + 2 * k4;
            h01[i] = *(const ulonglong2*)p;
            h23[i] = *(const ulonglong2*)(p + 4);
        }
#pragma unroll
        for (int j = 0; j < 4; j++) {
            float4 w = *(const float4*)(sw + (size_t)(b * 64 + er + 16 * j) * 36 + k4);
            u64 w0 = pack2(w.x), w1 = pack2(w.y), w2 = pack2(w.z), w3 = pack2(w.w);
#pragma unroll
            for (int i = 0; i < 4; i++) {
                ffma2(acc2[i][j], h01[i].x, w0);
                ffma2(acc2[i][j], h01[i].y, w1);
                ffma2(acc2[i][j], h23[i].x, w2);
                ffma2(acc2[i][j], h23[i].y, w3);
            }
        }
    }
}

__global__ __launch_bounds__(NT, 1)
void gate_kernel(const float* __restrict__ H, const float* __restrict__ W,
                 float* __restrict__ out, int out_size)
{
    extern __shared__ char dynsm[];
    __shared__ float rinv[TM];
    __shared__ float sm_cnt[NE];
    __shared__ unsigned int is_last;
    __shared__ int fb_cnt;
    __shared__ int fb_list[TM];

    const int tid  = threadIdx.x;
    const int blk  = blockIdx.x;
    const int wid  = tid >> 5;
    const int lane = tid & 31;
    char* base = dynsm;
    const uint32_t dynb32 = smem_u32(base);

    if (tid == 0) fb_cnt = 0;
    if (tid < NE) sm_cnt[tid] = 0.f;

    const float* Hb = H + (size_t)blk * TM * DIM;
    float (*logits)[NE + 1] = (float(*)[NE + 1])base;

    u64 acc2[4][4];   // SIMT accumulators (live across the converge barrier)
#pragma unroll
    for (int i = 0; i < 4; i++)
#pragma unroll
        for (int j = 0; j < 4; j++) acc2[i][j] = 0ull;

    if (tid < 256) {
        // ============ HMMA domain: k in [0, KSB), barrier 1 ============
        float acc[2][4][4];
#pragma unroll
        for (int m = 0; m < 2; m++)
#pragma unroll
            for (int j = 0; j < 4; j++)
#pragma unroll
                for (int q = 0; q < 4; q++) acc[m][j][q] = 0.f;

        float4 ha[4];
        b_cpasync(dynb32, 0, 0, tid);
        b_cpasync(dynb32, 1, 1, tid);
        ldg_h(Hb, 0, tid, ha);
        sts_h(base, 0, tid, ha);
        for (int c = 0; c < NCH_H; c++) {
            const int bA = c & 1;
            const int bB = c % 3;
            const bool more = (c + 1 < NCH_H);
            if (more) { ldg_h(Hb, c + 1, tid, ha); cp_wait<1>(); }
            else      { cp_wait<0>(); }
            BARN(1, 256);
            compute_h(dynb32, bA, bB, wid, lane, acc);
            if (more) sts_h(base, bA ^ 1, tid, ha);
            if (c + 2 < NCH_H) b_cpasync(dynb32, c + 2, (c + 2) % 3, tid);
        }
        BARN(1, 256);   // all HMMA warps done reading A region before logits reuse

        // HMMA partials -> logits (kh0 writes, kh1 adds)
        const int mrow = (wid & 1) * 32;
        const int ncol = ((wid >> 1) & 1) * 32;
        const int kh   = wid >> 2;
        const int r  = lane >> 2;
        const int cb = (lane & 3) * 2;
        if (kh == 0) {
#pragma unroll
            for (int m = 0; m < 2; m++)
#pragma unroll
                for (int j = 0; j < 4; j++) {
                    logits[mrow + m * 16 + r][ncol + cb + j * 8]         = acc[m][j][0];
                    logits[mrow + m * 16 + r][ncol + cb + j * 8 + 1]     = acc[m][j][1];
                    logits[mrow + m * 16 + r + 8][ncol + cb + j * 8]     = acc[m][j][2];
                    logits[mrow + m * 16 + r + 8][ncol + cb + j * 8 + 1] = acc[m][j][3];
                }
        }
        BARN(1, 256);
        if (kh == 1) {
#pragma unroll
            for (int m = 0; m < 2; m++)
#pragma unroll
                for (int j = 0; j < 4; j++) {
                    logits[mrow + m * 16 + r][ncol + cb + j * 8]         += acc[m][j][0];
                    logits[mrow + m * 16 + r][ncol + cb + j * 8 + 1]     += acc[m][j][1];
                    logits[mrow + m * 16 + r + 8][ncol + cb + j * 8]     += acc[m][j][2];
                    logits[mrow + m * 16 + r + 8][ncol + cb + j * 8 + 1] += acc[m][j][3];
                }
        }
    } else {
        // ============ FFMA2 domain: k in [KSB, DIM), barrier 2 ============
        const int stid = tid - 256;
        float* sh = (float*)(base + SH_OFF);
        float* sw = (float*)(base + SW_OFF);
        float4 hv[4], wv[4];
        simt_ldg(Hb, W, KSB, stid, hv, wv);
        simt_sts(sh, sw, 0, stid, hv, wv);
        for (int cs = 0; cs < NCS; cs++) {
            const int b = cs & 1;
            const bool more = (cs + 1 < NCS);
            if (more) simt_ldg(Hb, W, KSB + (cs + 1) * KC2, stid, hv, wv);
            BARN(2, 128);   // sts(cs) visible; compute(cs-1) on b^1 done by all 128
            simt_compute(sh, sw, b, stid, acc2);
            if (more) simt_sts(sh, sw, b ^ 1, stid, hv, wv);
        }
    }
    __syncthreads();   // both domains done; HMMA partial fully in logits

    // SIMT threads add their exact fp32 partial (each (t,e) owned by one thread)
    if (tid >= 256) {
        const int stid = tid - 256;
        const int er = stid & 15, tr = stid >> 4;
#pragma unroll
        for (int i = 0; i < 4; i++)
#pragma unroll
            for (int j = 0; j < 4; j++) {
                float lo, hi;
                unpack2(acc2[i][j], lo, hi);
                const int t0 = 2 * (tr * 4 + i);
                logits[t0][er + 16 * j]     += lo;
                logits[t0 + 1][er + 16 * j] += hi;
            }
    }
    __syncthreads();

    // -------- near-tie detection: any adjacent gap in top-9 below TAU --------
    if (tid < TM) {
        float v[9];
#pragma unroll
        for (int j = 0; j < 9; j++) v[j] = -1e30f;
        for (int e = 0; e < NE; e++) {
            float nv = logits[tid][e];
#pragma unroll
            for (int j = 0; j < 9; j++) {
                if (nv > v[j]) { float t = v[j]; v[j] = nv; nv = t; }
            }
        }
        float mingap = 1e30f;
#pragma unroll
        for (int j = 0; j < 8; j++) mingap = fminf(mingap, v[j] - v[j + 1]);
        if (mingap < TAU) {
            int ix = atomicAdd(&fb_cnt, 1);
            fb_list[ix] = tid;
        }
    }
    __syncthreads();

    // -------- exact fp32 sequential-k fallback (R0 bit-exact), 4 tokens/pass --------
    if (tid < 256) {
        const int nfb = fb_cnt;
        for (int f0 = 0; f0 < nfb; f0 += 4) {
            const int fi = f0 + (tid >> 6);
            if (fi < nfb) {
                const int t = fb_list[fi];
                const int e = tid & 63;
                const float* hr = H + (size_t)(blk * TM + t) * DIM;
                const float* wr = W + (size_t)e * DIM;
                float a = 0.f;
                for (int k = 0; k < DIM; k += 4) {
                    float4 hvx = *(const float4*)(hr + k);
                    float4 wvx = *(const float4*)(wr + k);
                    a = fmaf(hvx.x, wvx.x, a);
                    a = fmaf(hvx.y, wvx.y, a);
                    a = fmaf(hvx.z, wvx.z, a);
                    a = fmaf(hvx.w, wvx.w, a);
                }
                logits[t][e] = a;
            }
        }
    }
    __syncthreads();

    // -------- per-token softmax + top-8 (proven R0 pipeline) --------
    if (tid < TM) {
        float m = -1e30f;
        for (int e = 0; e < NE; e++) m = fmaxf(m, logits[tid][e]);

        float s = 0.f;
        float val[KTOP]; int idx[KTOP];
#pragma unroll
        for (int j = 0; j < KTOP; j++) { val[j] = -1.f; idx[j] = 0; }
        for (int e = 0; e < NE; e++) {
            float ex = __expf(logits[tid][e] - m);
            logits[tid][e] = ex;   // stash exp for mean-prob pass
            s += ex;
            float nv = ex; int ni = e;
#pragma unroll
            for (int j = 0; j < KTOP; j++) {
                if (nv > val[j]) {
                    float tv = val[j]; val[j] = nv; nv = tv;
                    int   ti = idx[j]; idx[j] = ni; ni = ti;
                }
            }
        }
        rinv[tid] = 1.f / s;

        float ts = 0.f;
#pragma unroll
        for (int j = 0; j < KTOP; j++) ts += val[j];
        const float tinv = 1.f / ts;

        const int gt = blk * TM + tid;
        float* ow = out + (size_t)gt * KTOP;
        float* oi = out + (size_t)NTOK * KTOP + (size_t)gt * KTOP;
#pragma unroll
        for (int j = 0; j < KTOP; j++) {
            ow[j] = val[j] * tinv;
            oi[j] = (float)idx[j];
            atomicAdd(&sm_cnt[idx[j]], 1.f);  // integer counts: order-exact
        }
    }
    __syncthreads();

    // -------- per-block mean-prob partial (4 parts x 16 tokens, threads 0..255) --------
    float* prS = (float*)base + PR_OFF;
    float* rcS = (float*)base + RC_OFF;
    float* rpS = (float*)base + RP_OFF;
    if (tid < 256) {
        const int e = tid & 63;
        const int p = tid >> 6;
        float sacc = 0.f;
        for (int t = p * 16; t < p * 16 + 16; t++)
            sacc += logits[t][e] * rinv[t];
        prS[p * NE + e] = sacc;
    }
    __syncthreads();
    if (tid < NE) {
        g_prob_part[blk][tid] = prS[tid] + prS[NE + tid] + prS[2 * NE + tid] + prS[3 * NE + tid];
        g_cnt_part[blk][tid]  = sm_cnt[tid];
    }

    // -------- last block finalizes the aux loss --------
    __threadfence();
    if (tid == 0)
        is_last = (atomicInc(&g_sync, NBLK - 1) == NBLK - 1);
    __syncthreads();
    if (is_last && tid < 256) {
        const int e = tid & 63;
        const int p = tid >> 6;       // 4 parts x 64 blocks, fixed order
        float c = 0.f, pm = 0.f;
        for (int b = p * 64; b < p * 64 + 64; b++) {
            c  += g_cnt_part[b][e];
            pm += g_prob_part[b][e];
        }
        rcS[p * NE + e] = c; rpS[p * NE + e] = pm;
    }
    __syncthreads();
    if (is_last && tid == 0) {
        float s = 0.f;
        for (int e2 = 0; e2 < NE; e2++) {
            float C = rcS[e2] + rcS[NE + e2] + rcS[2 * NE + e2] + rcS[3 * NE + e2];
            float P = rpS[e2] + rpS[NE + e2] + rpS[2 * NE + e2] + rpS[3 * NE + e2];
            s += (C / (float)(NTOK * KTOP)) * (P / (float)NTOK);
        }
        const int pos = NTOK * KTOP * 2;
        if (pos < out_size) out[pos] = ALPHA_C * (float)NE * s;
    }
}

extern "C" void kernel_launch(void* const* d_in, const int* in_sizes, int n_in,
                              void* d_out, int out_size)
{
    const float* H = (const float*)d_in[0];   // hidden_states (16384, 2048) fp32
    const float* W = (const float*)d_in[1];   // weight (64, 2048) fp32
    float* out = (float*)d_out;

    wconv_kernel<<<NE * DIM / 4 / 256, 256>>>(W);
    cudaFuncSetAttribute(gate_kernel, cudaFuncAttributeMaxDynamicSharedMemorySize, DYN_BYTES);
    gate_kernel<<<NBLK, NT, DYN_BYTES>>>(H, W, out, out_size);
}